// round 1
// baseline (speedup 1.0000x reference)
#include <cuda_runtime.h>
#include <math.h>

#define B 128
#define L 1024
#define P_TX 10.0f
#define P_NOISE 6.2946e-14f

// Scratch (no allocations allowed in kernel_launch)
__device__ float g_Py[B * L];   // P * y[b,j]
__device__ float g_R[B * L];    // Shannon rate per (b,k)
__device__ float g_inv[B];      // 1 / sum_k R[b,k]

__inline__ __device__ float warp_reduce(float v) {
    #pragma unroll
    for (int o = 16; o; o >>= 1) v += __shfl_down_sync(0xffffffffu, v, o);
    return v;
}

// ---- Kernel 1: Py = P * prob[:,1] ----
__global__ void py_kernel(const float* __restrict__ prob) {
    int i = blockIdx.x * blockDim.x + threadIdx.x;
    if (i < B * L) g_Py[i] = P_TX * prob[2 * i + 1];
}

// ---- Kernel 2: one block per (b,k) row; R[b,k] ----
// 128 threads, each handles 2 float4 (8 floats) of the 1024-float row.
__global__ void __launch_bounds__(128, 16) row_kernel(const float* __restrict__ H) {
    const int idx = blockIdx.x;          // b*L + k
    const int b   = idx >> 10;
    const int k   = idx & (L - 1);
    const int tid = threadIdx.x;

    const float4* __restrict__ row = reinterpret_cast<const float4*>(H + (size_t)idx * L);
    const float*  __restrict__ Py  = g_Py + b * L;

    float acc = 0.0f;
    #pragma unroll
    for (int t = tid; t < L / 4; t += 128) {
        float4 h = __ldg(row + t);
        int j = t * 4;
        acc = fmaf(h.x * h.x, __ldg(Py + j + 0), acc);
        acc = fmaf(h.y * h.y, __ldg(Py + j + 1), acc);
        acc = fmaf(h.z * h.z, __ldg(Py + j + 2), acc);
        acc = fmaf(h.w * h.w, __ldg(Py + j + 3), acc);
    }

    __shared__ float s[4];
    acc = warp_reduce(acc);
    if ((tid & 31) == 0) s[tid >> 5] = acc;
    __syncthreads();
    if (tid == 0) {
        float total = s[0] + s[1] + s[2] + s[3];
        float d = __ldg(H + (size_t)idx * L + k);      // H[b,k,k]
        float signal = d * d * __ldg(Py + k);
        float interf = total - signal;
        g_R[idx] = log1pf(signal / (interf + P_NOISE)) * 1.4426950408889634f;
    }
}

// ---- Kernel 3: per-batch 1/sum(R) ----
__global__ void __launch_bounds__(256) batch_kernel() {
    const int b = blockIdx.x;
    const int tid = threadIdx.x;
    float acc = 0.0f;
    #pragma unroll
    for (int t = tid; t < L; t += 256) acc += g_R[b * L + t];
    __shared__ float s[8];
    acc = warp_reduce(acc);
    if ((tid & 31) == 0) s[tid >> 5] = acc;
    __syncthreads();
    if (tid == 0) {
        float sum = 0.0f;
        #pragma unroll
        for (int w = 0; w < 8; w++) sum += s[w];
        g_inv[b] = 1.0f / sum;
    }
}

// ---- Kernel 4: mean over batches -> out ----
__global__ void __launch_bounds__(128) final_kernel(float* __restrict__ out) {
    const int tid = threadIdx.x;
    float v = (tid < B) ? g_inv[tid] : 0.0f;
    __shared__ float s[4];
    v = warp_reduce(v);
    if ((tid & 31) == 0) s[tid >> 5] = v;
    __syncthreads();
    if (tid == 0) out[0] = (s[0] + s[1] + s[2] + s[3]) * (1.0f / (float)B);
}

extern "C" void kernel_launch(void* const* d_in, const int* in_sizes, int n_in,
                              void* d_out, int out_size) {
    // Identify inputs by size (prob = 2*B*L, H = B*L*L)
    const float* prob = (const float*)d_in[0];
    const float* H    = (const float*)d_in[1];
    if (in_sizes[0] != 2 * B * L) { prob = (const float*)d_in[1]; H = (const float*)d_in[0]; }

    py_kernel<<<(B * L + 255) / 256, 256>>>(prob);
    row_kernel<<<B * L, 128>>>(H);
    batch_kernel<<<B, 256>>>();
    final_kernel<<<1, 128>>>((float*)d_out);
}

// round 2
// speedup vs baseline: 1.1604x; 1.1604x over previous
#include <cuda_runtime.h>
#include <math.h>

#define B 128
#define L 1024
#define P_TX 10.0f
#define P_NOISE 6.2946e-14f

// Scratch (no allocations allowed)
__device__ float g_Py[B * L];   // P * y[b,j]
__device__ float g_R[B * L];    // Shannon rate per (b,k)

__inline__ __device__ float warp_reduce(float v) {
    #pragma unroll
    for (int o = 16; o; o >>= 1) v += __shfl_down_sync(0xffffffffu, v, o);
    return v;
}

// ---- Kernel 1: Py = P * prob[:,1] (vector-friendly layout) ----
__global__ void py_kernel(const float* __restrict__ prob) {
    int i = blockIdx.x * blockDim.x + threadIdx.x;
    if (i < B * L) g_Py[i] = P_TX * prob[2 * i + 1];
}

// ---- Kernel 2: warp-per-row; 8 rows per 256-thread block ----
// Each lane: 8 iterations of (H float4, Py float4), shfl reduce, lane0 epilogue.
__global__ void __launch_bounds__(256) row_kernel(const float* __restrict__ H) {
    const int row  = blockIdx.x * 8 + (threadIdx.x >> 5);   // global row in [0, B*L)
    const int lane = threadIdx.x & 31;
    const int b    = row >> 10;
    const int k    = row & (L - 1);

    const float4* __restrict__ h4 = reinterpret_cast<const float4*>(H + (size_t)row * L);
    const float4* __restrict__ p4 = reinterpret_cast<const float4*>(g_Py + b * L);

    float acc = 0.0f;
    #pragma unroll
    for (int i = 0; i < 8; i++) {
        float4 h = __ldg(h4 + i * 32 + lane);
        float4 p = __ldg(p4 + i * 32 + lane);
        acc = fmaf(h.x * h.x, p.x, acc);
        acc = fmaf(h.y * h.y, p.y, acc);
        acc = fmaf(h.z * h.z, p.z, acc);
        acc = fmaf(h.w * h.w, p.w, acc);
    }

    acc = warp_reduce(acc);

    if (lane == 0) {
        float d      = __ldg(H + (size_t)row * L + k);      // H[b,k,k] (L1 hit: just streamed)
        float signal = d * d * __ldg(g_Py + b * L + k);
        float interf = acc - signal;
        g_R[row] = log1pf(signal / (interf + P_NOISE)) * 1.4426950408889634f;
    }
}

// ---- Kernel 3: fused per-batch 1/sum and mean -> out ----
// One block, 1024 threads = 32 warps; each warp handles 4 batches.
__global__ void __launch_bounds__(1024) finalize_kernel(float* __restrict__ out) {
    const int wid  = threadIdx.x >> 5;
    const int lane = threadIdx.x & 31;

    float inv_acc = 0.0f;
    #pragma unroll
    for (int rep = 0; rep < 4; rep++) {
        int bidx = wid * 4 + rep;                 // batch index
        const float4* __restrict__ r4 = reinterpret_cast<const float4*>(g_R + bidx * L);
        float s = 0.0f;
        #pragma unroll
        for (int i = 0; i < 8; i++) {
            float4 r = r4[i * 32 + lane];
            s += (r.x + r.y) + (r.z + r.w);
        }
        s = warp_reduce(s);
        if (lane == 0) inv_acc += 1.0f / s;
    }

    __shared__ float sm[32];
    if (lane == 0) sm[wid] = inv_acc;
    __syncthreads();
    if (wid == 0) {
        float v = sm[lane];
        v = warp_reduce(v);
        if (lane == 0) out[0] = v * (1.0f / (float)B);
    }
}

extern "C" void kernel_launch(void* const* d_in, const int* in_sizes, int n_in,
                              void* d_out, int out_size) {
    const float* prob = (const float*)d_in[0];
    const float* H    = (const float*)d_in[1];
    if (in_sizes[0] != 2 * B * L) { prob = (const float*)d_in[1]; H = (const float*)d_in[0]; }

    py_kernel<<<(B * L + 255) / 256, 256>>>(prob);
    row_kernel<<<(B * L) / 8, 256>>>(H);
    finalize_kernel<<<1, 1024>>>((float*)d_out);
}